// round 2
// baseline (speedup 1.0000x reference)
#include <cuda_runtime.h>

#define S_LEN   16384
#define D_MODEL 1280
#define D3      3840
#define H_NUM   16
#define HDIM    80
#define WSIZE   64
#define NW      256

// Scratch (device-global; no runtime allocation allowed)
__device__ float g_qkv[(size_t)S_LEN * D3];       // [S, 3*D]  q|k|v each [S, H*HD]
__device__ float g_attn[(size_t)S_LEN * D_MODEL]; // attention output [S, H*HD]

// ---------------------------------------------------------------------------
// SGEMM: C[m][n] = sum_k A[m][k] * W[n][k] + bias[n]
// A: [M,K] row-major, W: [N,K] row-major (i.e. C = A @ W^T + b)
// 128x128x16 block tile, 8x8 per thread, 256 threads.
// M % 128 == 0, N % 128 == 0, K % 16 == 0 guaranteed for this problem.
// ---------------------------------------------------------------------------
__global__ __launch_bounds__(256) void sgemm_nt_bias(
    int M, int N, int K,
    const float* __restrict__ A, const float* __restrict__ W,
    const float* __restrict__ bias, float* __restrict__ C)
{
    const int BM = 128, BN = 128, BK = 16;
    __shared__ float As[BK * BM];
    __shared__ float Ws[BK * BN];

    const int tid = threadIdx.x;
    const int blockCol = blockIdx.x;   // over N
    const int blockRow = blockIdx.y;   // over M

    const float* Ab = A + (size_t)blockRow * BM * K;
    const float* Wb = W + (size_t)blockCol * BN * K;
    float* Cb = C + (size_t)blockRow * BM * N + (size_t)blockCol * BN;

    // global->smem load mapping: each thread loads 2 float4 from A and 2 from W
    const int innerRow = tid >> 2;          // 0..63
    const int innerCol = (tid & 3) * 4;     // 0,4,8,12 (k offset)

    // compute mapping: 16x16 thread grid, 8x8 outputs each
    const int threadRow = tid >> 4;         // 0..15
    const int threadCol = tid & 15;         // 0..15

    float acc[8][8];
    #pragma unroll
    for (int i = 0; i < 8; i++)
        #pragma unroll
        for (int j = 0; j < 8; j++) acc[i][j] = 0.0f;

    float regM[8], regN[8];

    for (int kt = 0; kt < K; kt += BK) {
        // load tiles (transposed into smem: [k][m] / [k][n])
        #pragma unroll
        for (int off = 0; off < BM; off += 64) {
            float4 ta = *reinterpret_cast<const float4*>(
                Ab + (size_t)(innerRow + off) * K + kt + innerCol);
            As[(innerCol + 0) * BM + innerRow + off] = ta.x;
            As[(innerCol + 1) * BM + innerRow + off] = ta.y;
            As[(innerCol + 2) * BM + innerRow + off] = ta.z;
            As[(innerCol + 3) * BM + innerRow + off] = ta.w;
            float4 tw = *reinterpret_cast<const float4*>(
                Wb + (size_t)(innerRow + off) * K + kt + innerCol);
            Ws[(innerCol + 0) * BN + innerRow + off] = tw.x;
            Ws[(innerCol + 1) * BN + innerRow + off] = tw.y;
            Ws[(innerCol + 2) * BN + innerRow + off] = tw.z;
            Ws[(innerCol + 3) * BN + innerRow + off] = tw.w;
        }
        __syncthreads();

        #pragma unroll
        for (int kk = 0; kk < BK; kk++) {
            *reinterpret_cast<float4*>(&regM[0]) =
                *reinterpret_cast<const float4*>(&As[kk * BM + threadRow * 8]);
            *reinterpret_cast<float4*>(&regM[4]) =
                *reinterpret_cast<const float4*>(&As[kk * BM + threadRow * 8 + 4]);
            *reinterpret_cast<float4*>(&regN[0]) =
                *reinterpret_cast<const float4*>(&Ws[kk * BN + threadCol * 8]);
            *reinterpret_cast<float4*>(&regN[4]) =
                *reinterpret_cast<const float4*>(&Ws[kk * BN + threadCol * 8 + 4]);
            #pragma unroll
            for (int i = 0; i < 8; i++)
                #pragma unroll
                for (int j = 0; j < 8; j++)
                    acc[i][j] += regM[i] * regN[j];
        }
        __syncthreads();
    }

    float bs[8];
    #pragma unroll
    for (int j = 0; j < 8; j++)
        bs[j] = bias[blockCol * BN + threadCol * 8 + j];

    #pragma unroll
    for (int i = 0; i < 8; i++) {
        float* crow = Cb + (size_t)(threadRow * 8 + i) * N + threadCol * 8;
        #pragma unroll
        for (int j = 0; j < 8; j += 4) {
            float4 o;
            o.x = acc[i][j + 0] + bs[j + 0];
            o.y = acc[i][j + 1] + bs[j + 1];
            o.z = acc[i][j + 2] + bs[j + 2];
            o.w = acc[i][j + 3] + bs[j + 3];
            *reinterpret_cast<float4*>(&crow[j]) = o;
        }
    }
}

// ---------------------------------------------------------------------------
// RoPE in-place on q and k parts of g_qkv.
// rotate_half over HD=80: halves of 40.
//   new[d]    = x[d]*cos[d]    - x[d+40]*sin[d]        (d < 40)
//   new[d+40] = x[d+40]*cos[d+40] + x[d]*sin[d+40]
// One thread handles one (s, h, d<40) for both q and k.
// ---------------------------------------------------------------------------
__global__ void rope_kernel(const float* __restrict__ cosb,
                            const float* __restrict__ sinb)
{
    int idx = blockIdx.x * blockDim.x + threadIdx.x;
    const int total = S_LEN * H_NUM * 40;
    if (idx >= total) return;
    int d = idx % 40;
    int h = (idx / 40) % H_NUM;
    int s = idx / (40 * H_NUM);

    float c0 = cosb[s * HDIM + d];
    float c1 = cosb[s * HDIM + d + 40];
    float s0 = sinb[s * HDIM + d];
    float s1 = sinb[s * HDIM + d + 40];

    float* row = g_qkv + (size_t)s * D3;
    #pragma unroll
    for (int part = 0; part < 2; part++) {
        float* p = row + part * D_MODEL + h * HDIM + d;
        float x0 = p[0];
        float x1 = p[40];
        p[0]  = x0 * c0 - x1 * s0;
        p[40] = x1 * c1 + x0 * s1;
    }
}

// ---------------------------------------------------------------------------
// Windowed attention: one block per (window w, head h).
// smem: q[64][84], k[64][84], v[64][84], sc[64][65]  (dynamic, ~81KB)
// Scores: 4x4 microtile per thread; softmax: warp per 8 rows; O: 4x5 per thread.
// ---------------------------------------------------------------------------
#define QP 84
#define SCP 65
#define ATT_SMEM ((3 * 64 * QP + 64 * SCP) * (int)sizeof(float))

__global__ __launch_bounds__(256) void attn_kernel(const float* __restrict__ mask,
                                                   float* __restrict__ attn_out)
{
    extern __shared__ float smem[];
    float (*q)[QP]  = reinterpret_cast<float(*)[QP]>(smem);
    float (*k)[QP]  = reinterpret_cast<float(*)[QP]>(smem + 64 * QP);
    float (*v)[QP]  = reinterpret_cast<float(*)[QP]>(smem + 2 * 64 * QP);
    float (*sc)[SCP] = reinterpret_cast<float(*)[SCP]>(smem + 3 * 64 * QP);

    const int h = blockIdx.x;   // head
    const int w = blockIdx.y;   // window
    const int tid = threadIdx.x;

    // load q, k, v tiles: 64 rows x 80 floats each (20 float4 per row)
    for (int idx = tid; idx < 64 * 20; idx += 256) {
        int r  = idx / 20;
        int c4 = (idx % 20) * 4;
        const float* base = g_qkv + (size_t)(w * WSIZE + r) * D3 + h * HDIM + c4;
        *reinterpret_cast<float4*>(&q[r][c4]) =
            *reinterpret_cast<const float4*>(base);
        *reinterpret_cast<float4*>(&k[r][c4]) =
            *reinterpret_cast<const float4*>(base + D_MODEL);
        *reinterpret_cast<float4*>(&v[r][c4]) =
            *reinterpret_cast<const float4*>(base + 2 * D_MODEL);
    }
    __syncthreads();

    // scores: thread (tr,tc) computes rows tr*4..+3, cols tc*4..+3
    const int tr = tid >> 4;   // 0..15
    const int tc = tid & 15;   // 0..15
    {
        float acc[4][4];
        #pragma unroll
        for (int i = 0; i < 4; i++)
            #pragma unroll
            for (int j = 0; j < 4; j++) acc[i][j] = 0.0f;

        for (int d = 0; d < HDIM; d += 4) {
            float4 qa[4], kb[4];
            #pragma unroll
            for (int i = 0; i < 4; i++)
                qa[i] = *reinterpret_cast<const float4*>(&q[tr * 4 + i][d]);
            #pragma unroll
            for (int j = 0; j < 4; j++)
                kb[j] = *reinterpret_cast<const float4*>(&k[tc * 4 + j][d]);
            #pragma unroll
            for (int i = 0; i < 4; i++)
                #pragma unroll
                for (int j = 0; j < 4; j++)
                    acc[i][j] += qa[i].x * kb[j].x + qa[i].y * kb[j].y +
                                 qa[i].z * kb[j].z + qa[i].w * kb[j].w;
        }
        const float scale = 0.11180339887498949f;  // 1/sqrt(80)
        const float* mw = mask + (size_t)w * (WSIZE * WSIZE);
        #pragma unroll
        for (int i = 0; i < 4; i++)
            #pragma unroll
            for (int j = 0; j < 4; j++)
                sc[tr * 4 + i][tc * 4 + j] =
                    acc[i][j] * scale + mw[(tr * 4 + i) * WSIZE + tc * 4 + j];
    }
    __syncthreads();

    // softmax: warp `wid` handles rows wid*8 .. wid*8+7; lane covers j=lane, j=lane+32
    {
        const int wid  = tid >> 5;
        const int lane = tid & 31;
        #pragma unroll
        for (int rr = 0; rr < 8; rr++) {
            int r = wid * 8 + rr;
            float a0 = sc[r][lane];
            float a1 = sc[r][lane + 32];
            float m = fmaxf(a0, a1);
            #pragma unroll
            for (int off = 16; off > 0; off >>= 1)
                m = fmaxf(m, __shfl_xor_sync(0xffffffffu, m, off));
            float e0 = __expf(a0 - m);
            float e1 = __expf(a1 - m);
            float s = e0 + e1;
            #pragma unroll
            for (int off = 16; off > 0; off >>= 1)
                s += __shfl_xor_sync(0xffffffffu, s, off);
            float inv = __frcp_rn(s);
            sc[r][lane]      = e0 * inv;
            sc[r][lane + 32] = e1 * inv;
        }
    }
    __syncthreads();

    // O = P @ V : thread (tr,tc) computes rows tr*4..+3, cols tc*5..+4
    {
        float o[4][5];
        #pragma unroll
        for (int i = 0; i < 4; i++)
            #pragma unroll
            for (int c = 0; c < 5; c++) o[i][c] = 0.0f;

        #pragma unroll 4
        for (int j = 0; j < WSIZE; j++) {
            float p[4];
            #pragma unroll
            for (int i = 0; i < 4; i++) p[i] = sc[tr * 4 + i][j];
            float vv[5];
            #pragma unroll
            for (int c = 0; c < 5; c++) vv[c] = v[j][tc * 5 + c];
            #pragma unroll
            for (int i = 0; i < 4; i++)
                #pragma unroll
                for (int c = 0; c < 5; c++)
                    o[i][c] += p[i] * vv[c];
        }
        #pragma unroll
        for (int i = 0; i < 4; i++) {
            float* orow = attn_out + (size_t)(w * WSIZE + tr * 4 + i) * D_MODEL
                          + h * HDIM + tc * 5;
            #pragma unroll
            for (int c = 0; c < 5; c++) orow[c] = o[i][c];
        }
    }
}

// ---------------------------------------------------------------------------
// Launch
// ---------------------------------------------------------------------------
extern "C" void kernel_launch(void* const* d_in, const int* in_sizes, int n_in,
                              void* d_out, int out_size)
{
    const float* hs     = (const float*)d_in[0];
    const float* mask   = (const float*)d_in[1];
    const float* cosb   = (const float*)d_in[2];
    const float* sinb   = (const float*)d_in[3];
    const float* qkv_w  = (const float*)d_in[4];
    const float* qkv_b  = (const float*)d_in[5];
    const float* proj_w = (const float*)d_in[6];
    const float* proj_b = (const float*)d_in[7];
    float* out = (float*)d_out;

    float *qkv_ptr = nullptr, *attn_ptr = nullptr;
    cudaGetSymbolAddress((void**)&qkv_ptr, g_qkv);
    cudaGetSymbolAddress((void**)&attn_ptr, g_attn);
    cudaFuncSetAttribute(attn_kernel,
                         cudaFuncAttributeMaxDynamicSharedMemorySize, ATT_SMEM);

    // 1) QKV = hs @ qkv_w^T + qkv_b
    {
        dim3 grid(D3 / 128, S_LEN / 128);
        sgemm_nt_bias<<<grid, 256>>>(S_LEN, D3, D_MODEL, hs, qkv_w, qkv_b, qkv_ptr);
    }
    // 2) RoPE on q,k in-place
    {
        int total = S_LEN * H_NUM * 40;
        rope_kernel<<<(total + 255) / 256, 256>>>(cosb, sinb);
    }
    // 3) windowed attention -> g_attn [S, H*HD]
    {
        dim3 grid(H_NUM, NW);
        attn_kernel<<<grid, 256, ATT_SMEM>>>(mask, attn_ptr);
    }
    // 4) out = g_attn @ proj_w^T + proj_b
    {
        dim3 grid(D_MODEL / 128, S_LEN / 128);
        sgemm_nt_bias<<<grid, 256>>>(S_LEN, D_MODEL, D_MODEL, attn_ptr, proj_w, proj_b, out);
    }
}

// round 3
// speedup vs baseline: 2.9626x; 2.9626x over previous
#include <cuda_runtime.h>
#include <cstdint>

#define S_LEN   16384
#define D_MODEL 1280
#define D3      3840
#define H_NUM   16
#define HDIM    80
#define WSIZE   64
#define NW      256

// Scratch (device-global; no runtime allocation allowed)
__device__ float g_qkv[(size_t)S_LEN * D3];       // [S, 3*D]  q|k|v each [S, H*HD]
__device__ float g_attn[(size_t)S_LEN * D_MODEL]; // attention output [S, H*HD]

// ---------------------------------------------------------------------------
// TF32 tensor-core GEMM: C[m][n] = sum_k A[m][k]*W[n][k] + bias[n]
// (C = A @ W^T + b). A:[M,K] row-major, W:[N,K] row-major (both K-contig,
// i.e. mma row.col "TN" layout).
// CTA tile 128x128x32, 8 warps (4 x 2), warp tile 32x64, m16n8k8 tf32 MMA.
// cp.async double-buffered smem, fp32 in smem, cvt.rna.tf32 at fragment load.
// M%128==0, N%128==0, K%32==0 guaranteed here.
// ---------------------------------------------------------------------------
#define GSK   36                 // padded smem row stride (floats) - conflict-free
#define GTILE (128 * GSK)        // floats per operand tile
#define GEMM_SMEM (2 * 2 * GTILE * 4)  // 2 stages x (A+W) x 4B = 73728 B

__device__ __forceinline__ uint32_t f2tf32(float x) {
    uint32_t r;
    asm volatile("cvt.rna.tf32.f32 %0, %1;" : "=r"(r) : "f"(x));
    return r;
}

__device__ __forceinline__ void cp_async16(uint32_t dst, const void* src) {
    asm volatile("cp.async.cg.shared.global [%0], [%1], 16;\n" :: "r"(dst), "l"(src));
}
__device__ __forceinline__ void cp_commit() {
    asm volatile("cp.async.commit_group;\n" ::: "memory");
}
template <int N>
__device__ __forceinline__ void cp_wait() {
    asm volatile("cp.async.wait_group %0;\n" :: "n"(N) : "memory");
}

__global__ __launch_bounds__(256, 2) void gemm_tf32_nt_bias(
    int M, int N, int K,
    const float* __restrict__ A, const float* __restrict__ W,
    const float* __restrict__ bias, float* __restrict__ C)
{
    extern __shared__ float smem[];
    const int tid  = threadIdx.x;
    const int wid  = tid >> 5;
    const int lane = tid & 31;
    const int warpRow = wid & 3;   // 4 warps over M (32 rows each)
    const int warpCol = wid >> 2;  // 2 warps over N (64 cols each)
    const int gr = lane >> 2;      // 0..7
    const int gc = lane & 3;       // 0..3

    const int blockCol = blockIdx.x;  // over N
    const int blockRow = blockIdx.y;  // over M

    const float* Abase = A + (size_t)blockRow * 128 * K;
    const float* Wbase = W + (size_t)blockCol * 128 * K;

    uint32_t smem_u32 = (uint32_t)__cvta_generic_to_shared(smem);

    // per-thread load slots: 4 float4 per operand tile
    int lrow[4], lcol[4];
    #pragma unroll
    for (int it = 0; it < 4; it++) {
        int fi = tid + it * 256;        // 0..1023
        lrow[it] = fi >> 3;             // 0..127
        lcol[it] = (fi & 7) * 4;        // 0..28
    }

    float acc[2][8][4];
    #pragma unroll
    for (int mt = 0; mt < 2; mt++)
        #pragma unroll
        for (int nt = 0; nt < 8; nt++)
            #pragma unroll
            for (int c = 0; c < 4; c++) acc[mt][nt][c] = 0.0f;

    const int niter = K >> 5;  // K/32

    // ---- issue stage-0 loads
    {
        uint32_t sA = smem_u32;
        uint32_t sW = smem_u32 + GTILE * 4;
        #pragma unroll
        for (int it = 0; it < 4; it++) {
            uint32_t so = (uint32_t)(lrow[it] * GSK + lcol[it]) * 4u;
            cp_async16(sA + so, Abase + (size_t)lrow[it] * K + lcol[it]);
            cp_async16(sW + so, Wbase + (size_t)lrow[it] * K + lcol[it]);
        }
        cp_commit();
    }

    for (int i = 0; i < niter; i++) {
        // ---- issue next-stage loads
        if (i + 1 < niter) {
            int kt = (i + 1) << 5;
            uint32_t sA = smem_u32 + ((i + 1) & 1) * 2 * GTILE * 4;
            uint32_t sW = sA + GTILE * 4;
            #pragma unroll
            for (int it = 0; it < 4; it++) {
                uint32_t so = (uint32_t)(lrow[it] * GSK + lcol[it]) * 4u;
                cp_async16(sA + so, Abase + (size_t)lrow[it] * K + kt + lcol[it]);
                cp_async16(sW + so, Wbase + (size_t)lrow[it] * K + kt + lcol[it]);
            }
            cp_commit();
            cp_wait<1>();
        } else {
            cp_wait<0>();
        }
        __syncthreads();

        const float* As = smem + (i & 1) * 2 * GTILE;
        const float* Ws = As + GTILE;

        #pragma unroll
        for (int ks = 0; ks < 4; ks++) {
            const int k0 = ks * 8;
            uint32_t af[2][4];
            #pragma unroll
            for (int mt = 0; mt < 2; mt++) {
                int r0 = warpRow * 32 + mt * 16;
                af[mt][0] = f2tf32(As[(r0 + gr)     * GSK + k0 + gc]);
                af[mt][1] = f2tf32(As[(r0 + gr + 8) * GSK + k0 + gc]);
                af[mt][2] = f2tf32(As[(r0 + gr)     * GSK + k0 + gc + 4]);
                af[mt][3] = f2tf32(As[(r0 + gr + 8) * GSK + k0 + gc + 4]);
            }
            uint32_t bf[8][2];
            #pragma unroll
            for (int nt = 0; nt < 8; nt++) {
                int n0 = warpCol * 64 + nt * 8 + gr;
                bf[nt][0] = f2tf32(Ws[n0 * GSK + k0 + gc]);
                bf[nt][1] = f2tf32(Ws[n0 * GSK + k0 + gc + 4]);
            }
            #pragma unroll
            for (int mt = 0; mt < 2; mt++)
                #pragma unroll
                for (int nt = 0; nt < 8; nt++) {
                    asm volatile(
                        "mma.sync.aligned.m16n8k8.row.col.f32.tf32.tf32.f32 "
                        "{%0,%1,%2,%3}, {%4,%5,%6,%7}, {%8,%9}, {%0,%1,%2,%3};"
                        : "+f"(acc[mt][nt][0]), "+f"(acc[mt][nt][1]),
                          "+f"(acc[mt][nt][2]), "+f"(acc[mt][nt][3])
                        : "r"(af[mt][0]), "r"(af[mt][1]),
                          "r"(af[mt][2]), "r"(af[mt][3]),
                          "r"(bf[nt][0]), "r"(bf[nt][1]));
                }
        }
        __syncthreads();
    }

    // ---- epilogue: add bias, store (float2 per c0/c1 pair)
    const int colBase = blockCol * 128 + warpCol * 64;
    const int rowBase = blockRow * 128 + warpRow * 32;
    #pragma unroll
    for (int nt = 0; nt < 8; nt++) {
        int col = colBase + nt * 8 + gc * 2;
        float b0 = bias[col];
        float b1 = bias[col + 1];
        #pragma unroll
        for (int mt = 0; mt < 2; mt++) {
            int r0 = rowBase + mt * 16 + gr;
            float2 v0 = make_float2(acc[mt][nt][0] + b0, acc[mt][nt][1] + b1);
            float2 v1 = make_float2(acc[mt][nt][2] + b0, acc[mt][nt][3] + b1);
            *reinterpret_cast<float2*>(C + (size_t)r0 * N + col)       = v0;
            *reinterpret_cast<float2*>(C + (size_t)(r0 + 8) * N + col) = v1;
        }
    }
}

// ---------------------------------------------------------------------------
// RoPE in-place on q and k parts of g_qkv.
// ---------------------------------------------------------------------------
__global__ void rope_kernel(const float* __restrict__ cosb,
                            const float* __restrict__ sinb)
{
    int idx = blockIdx.x * blockDim.x + threadIdx.x;
    const int total = S_LEN * H_NUM * 40;
    if (idx >= total) return;
    int d = idx % 40;
    int h = (idx / 40) % H_NUM;
    int s = idx / (40 * H_NUM);

    float c0 = cosb[s * HDIM + d];
    float c1 = cosb[s * HDIM + d + 40];
    float s0 = sinb[s * HDIM + d];
    float s1 = sinb[s * HDIM + d + 40];

    float* row = g_qkv + (size_t)s * D3;
    #pragma unroll
    for (int part = 0; part < 2; part++) {
        float* p = row + part * D_MODEL + h * HDIM + d;
        float x0 = p[0];
        float x1 = p[40];
        p[0]  = x0 * c0 - x1 * s0;
        p[40] = x1 * c1 + x0 * s1;
    }
}

// ---------------------------------------------------------------------------
// Windowed attention: one block per (window w, head h). (unchanged)
// ---------------------------------------------------------------------------
#define QP 84
#define SCP 65
#define ATT_SMEM ((3 * 64 * QP + 64 * SCP) * (int)sizeof(float))

__global__ __launch_bounds__(256) void attn_kernel(const float* __restrict__ mask,
                                                   float* __restrict__ attn_out)
{
    extern __shared__ float smem[];
    float (*q)[QP]  = reinterpret_cast<float(*)[QP]>(smem);
    float (*k)[QP]  = reinterpret_cast<float(*)[QP]>(smem + 64 * QP);
    float (*v)[QP]  = reinterpret_cast<float(*)[QP]>(smem + 2 * 64 * QP);
    float (*sc)[SCP] = reinterpret_cast<float(*)[SCP]>(smem + 3 * 64 * QP);

    const int h = blockIdx.x;   // head
    const int w = blockIdx.y;   // window
    const int tid = threadIdx.x;

    for (int idx = tid; idx < 64 * 20; idx += 256) {
        int r  = idx / 20;
        int c4 = (idx % 20) * 4;
        const float* base = g_qkv + (size_t)(w * WSIZE + r) * D3 + h * HDIM + c4;
        *reinterpret_cast<float4*>(&q[r][c4]) =
            *reinterpret_cast<const float4*>(base);
        *reinterpret_cast<float4*>(&k[r][c4]) =
            *reinterpret_cast<const float4*>(base + D_MODEL);
        *reinterpret_cast<float4*>(&v[r][c4]) =
            *reinterpret_cast<const float4*>(base + 2 * D_MODEL);
    }
    __syncthreads();

    const int tr = tid >> 4;   // 0..15
    const int tc = tid & 15;   // 0..15
    {
        float acc[4][4];
        #pragma unroll
        for (int i = 0; i < 4; i++)
            #pragma unroll
            for (int j = 0; j < 4; j++) acc[i][j] = 0.0f;

        for (int d = 0; d < HDIM; d += 4) {
            float4 qa[4], kb[4];
            #pragma unroll
            for (int i = 0; i < 4; i++)
                qa[i] = *reinterpret_cast<const float4*>(&q[tr * 4 + i][d]);
            #pragma unroll
            for (int j = 0; j < 4; j++)
                kb[j] = *reinterpret_cast<const float4*>(&k[tc * 4 + j][d]);
            #pragma unroll
            for (int i = 0; i < 4; i++)
                #pragma unroll
                for (int j = 0; j < 4; j++)
                    acc[i][j] += qa[i].x * kb[j].x + qa[i].y * kb[j].y +
                                 qa[i].z * kb[j].z + qa[i].w * kb[j].w;
        }
        const float scale = 0.11180339887498949f;  // 1/sqrt(80)
        const float* mw = mask + (size_t)w * (WSIZE * WSIZE);
        #pragma unroll
        for (int i = 0; i < 4; i++)
            #pragma unroll
            for (int j = 0; j < 4; j++)
                sc[tr * 4 + i][tc * 4 + j] =
                    acc[i][j] * scale + mw[(tr * 4 + i) * WSIZE + tc * 4 + j];
    }
    __syncthreads();

    {
        const int wd   = tid >> 5;
        const int lane = tid & 31;
        #pragma unroll
        for (int rr = 0; rr < 8; rr++) {
            int r = wd * 8 + rr;
            float a0 = sc[r][lane];
            float a1 = sc[r][lane + 32];
            float m = fmaxf(a0, a1);
            #pragma unroll
            for (int off = 16; off > 0; off >>= 1)
                m = fmaxf(m, __shfl_xor_sync(0xffffffffu, m, off));
            float e0 = __expf(a0 - m);
            float e1 = __expf(a1 - m);
            float s = e0 + e1;
            #pragma unroll
            for (int off = 16; off > 0; off >>= 1)
                s += __shfl_xor_sync(0xffffffffu, s, off);
            float inv = __frcp_rn(s);
            sc[r][lane]      = e0 * inv;
            sc[r][lane + 32] = e1 * inv;
        }
    }
    __syncthreads();

    {
        float o[4][5];
        #pragma unroll
        for (int i = 0; i < 4; i++)
            #pragma unroll
            for (int c = 0; c < 5; c++) o[i][c] = 0.0f;

        #pragma unroll 4
        for (int j = 0; j < WSIZE; j++) {
            float p[4];
            #pragma unroll
            for (int i = 0; i < 4; i++) p[i] = sc[tr * 4 + i][j];
            float vv[5];
            #pragma unroll
            for (int c = 0; c < 5; c++) vv[c] = v[j][tc * 5 + c];
            #pragma unroll
            for (int i = 0; i < 4; i++)
                #pragma unroll
                for (int c = 0; c < 5; c++)
                    o[i][c] += p[i] * vv[c];
        }
        #pragma unroll
        for (int i = 0; i < 4; i++) {
            float* orow = attn_out + (size_t)(w * WSIZE + tr * 4 + i) * D_MODEL
                          + h * HDIM + tc * 5;
            #pragma unroll
            for (int c = 0; c < 5; c++) orow[c] = o[i][c];
        }
    }
}

// ---------------------------------------------------------------------------
// Launch
// ---------------------------------------------------------------------------
extern "C" void kernel_launch(void* const* d_in, const int* in_sizes, int n_in,
                              void* d_out, int out_size)
{
    const float* hs     = (const float*)d_in[0];
    const float* mask   = (const float*)d_in[1];
    const float* cosb   = (const float*)d_in[2];
    const float* sinb   = (const float*)d_in[3];
    const float* qkv_w  = (const float*)d_in[4];
    const float* qkv_b  = (const float*)d_in[5];
    const float* proj_w = (const float*)d_in[6];
    const float* proj_b = (const float*)d_in[7];
    float* out = (float*)d_out;

    float *qkv_ptr = nullptr, *attn_ptr = nullptr;
    cudaGetSymbolAddress((void**)&qkv_ptr, g_qkv);
    cudaGetSymbolAddress((void**)&attn_ptr, g_attn);
    cudaFuncSetAttribute(attn_kernel,
                         cudaFuncAttributeMaxDynamicSharedMemorySize, ATT_SMEM);
    cudaFuncSetAttribute(gemm_tf32_nt_bias,
                         cudaFuncAttributeMaxDynamicSharedMemorySize, GEMM_SMEM);

    // 1) QKV = hs @ qkv_w^T + qkv_b
    {
        dim3 grid(D3 / 128, S_LEN / 128);
        gemm_tf32_nt_bias<<<grid, 256, GEMM_SMEM>>>(S_LEN, D3, D_MODEL,
                                                    hs, qkv_w, qkv_b, qkv_ptr);
    }
    // 2) RoPE on q,k in-place
    {
        int total = S_LEN * H_NUM * 40;
        rope_kernel<<<(total + 255) / 256, 256>>>(cosb, sinb);
    }
    // 3) windowed attention -> g_attn [S, H*HD]
    {
        dim3 grid(H_NUM, NW);
        attn_kernel<<<grid, 256, ATT_SMEM>>>(mask, attn_ptr);
    }
    // 4) out = g_attn @ proj_w^T + proj_b
    {
        dim3 grid(D_MODEL / 128, S_LEN / 128);
        gemm_tf32_nt_bias<<<grid, 256, GEMM_SMEM>>>(S_LEN, D_MODEL, D_MODEL,
                                                    attn_ptr, proj_w, proj_b, out);
    }
}